// round 1
// baseline (speedup 1.0000x reference)
#include <cuda_runtime.h>
#include <math.h>
#include <stdint.h>

// Problem constants (fixed shapes from reference)
#define N_EMB   50000
#define D       128
#define B_USERS 64
#define L_SEQ   512
#define P0_N    200000
#define P1_N    50000
#define NEG_MSC 4
#define EPSF    1e-8f
#define BL      (B_USERS * L_SEQ)   // 32768

// ---------------- scratch (static device arrays; no allocation in launch) ----
__device__ double g_acc[3];                       // [0]=edge0 sum, [1]=edge1 sum, [2]=seq sum (of logsig / log terms, pre-negation)
__device__ float  g_I   [BL * D];                 // 16 MB  I rows (L,D) per user
__device__ float  g_q   [BL * D];
__device__ float  g_k   [BL * D];
__device__ float  g_v   [BL * D];
__device__ float  g_att [B_USERS * L_SEQ * L_SEQ];// 64 MB  att[b][j][i]
__device__ float  g_bmat[BL * D];
__device__ float  g_o   [BL * D];

// ---------------- helpers ----------------------------------------------------
__device__ __forceinline__ float warp_sum(float v) {
    #pragma unroll
    for (int o = 16; o > 0; o >>= 1) v += __shfl_xor_sync(0xffffffffu, v, o);
    return v;
}
__device__ __forceinline__ float warp_max(float v) {
    #pragma unroll
    for (int o = 16; o > 0; o >>= 1) v = fmaxf(v, __shfl_xor_sync(0xffffffffu, v, o));
    return v;
}
__device__ __forceinline__ float logsigf(float x) {
    return logf(1.0f / (1.0f + expf(-x)) + EPSF);
}
// per-block reduce of (lane0-held) terms then one double atomic
__device__ __forceinline__ void block_acc(float term, int accIdx) {
    __shared__ float s_red[8];
    int lane = threadIdx.x & 31, w = threadIdx.x >> 5;
    if (lane == 0) s_red[w] = term;
    __syncthreads();
    if (threadIdx.x == 0) {
        float t = 0.f;
        int nw = blockDim.x >> 5;
        #pragma unroll
        for (int i = 0; i < 8; i++) if (i < nw) t += s_red[i];
        atomicAdd(&g_acc[accIdx], (double)t);
    }
}

// ---------------- init -------------------------------------------------------
__global__ void k_zero() {
    if (threadIdx.x < 3) g_acc[threadIdx.x] = 0.0;
}

// ---------------- edge task 0: 2*P0 simple dots ------------------------------
// warp per item; item < P0 -> pos pair (sign +), else neg pair (sign -)
__global__ void k_edge0(const float4* __restrict__ E4,
                        const int2* __restrict__ pe, const int2* __restrict__ ne) {
    int gw   = (blockIdx.x * blockDim.x + threadIdx.x) >> 5;
    int lane = threadIdx.x & 31;
    float term = 0.f;
    if (gw < 2 * P0_N) {
        int2 pr; float sign;
        if (gw < P0_N) { pr = pe[gw];          sign =  1.f; }
        else           { pr = ne[gw - P0_N];   sign = -1.f; }
        float4 av = E4[(size_t)pr.x * (D/4) + lane];
        float4 bv = E4[(size_t)pr.y * (D/4) + lane];
        float p = av.x*bv.x + av.y*bv.y + av.z*bv.z + av.w*bv.w;
        p = warp_sum(p);
        if (lane == 0) term = logsigf(sign * p);
    }
    block_acc(term, 0);
}

// ---------------- edge task 1: ranking with tiled negatives ------------------
// warp per i in [0, 4*P1); j = i % P1; 3 dots, 2 logsig terms
__global__ void k_edge1(const float4* __restrict__ E4,
                        const int2* __restrict__ pe1, const int2* __restrict__ ne1) {
    int gw   = (blockIdx.x * blockDim.x + threadIdx.x) >> 5;
    int lane = threadIdx.x & 31;
    float term = 0.f;
    if (gw < P1_N * NEG_MSC) {
        int j = gw % P1_N;
        int2 pp = pe1[j];
        int2 np = ne1[gw];
        float4 ph = E4[(size_t)pp.x * (D/4) + lane];
        float4 pt = E4[(size_t)pp.y * (D/4) + lane];
        float4 nh = E4[(size_t)np.x * (D/4) + lane];
        float4 nt = E4[(size_t)np.y * (D/4) + lane];
        float sp = ph.x*pt.x + ph.y*pt.y + ph.z*pt.z + ph.w*pt.w;
        float sh = nh.x*pt.x + nh.y*pt.y + nh.z*pt.z + nh.w*pt.w;
        float st = ph.x*nt.x + ph.y*nt.y + ph.z*nt.z + ph.w*nt.w;
        sp = warp_sum(sp); sh = warp_sum(sh); st = warp_sum(st);
        if (lane == 0) term = logsigf(sp - sh) + logsigf(sp - st);
    }
    block_acc(term, 1);
}

// ---------------- build I rows: I[b,l,:] = emb[q] + W_rep[:, c] --------------
__global__ void k_buildI(const float4* __restrict__ E4, const float* __restrict__ Wrep,
                         const int* __restrict__ qseq, const int* __restrict__ cseq) {
    int row  = (blockIdx.x * blockDim.x + threadIdx.x) >> 5;   // 0..BL-1
    int lane = threadIdx.x & 31;
    int q = qseq[row];
    int c = cseq[row];
    float4 e = E4[(size_t)q * (D/4) + lane];
    int d0 = lane * 4;
    e.x += Wrep[(d0 + 0) * 2 + c];
    e.y += Wrep[(d0 + 1) * 2 + c];
    e.z += Wrep[(d0 + 2) * 2 + c];
    e.w += Wrep[(d0 + 3) * 2 + c];
    ((float4*)g_I)[(size_t)row * (D/4) + lane] = e;
}

// ---------------- GEMM NT: C[M,N] = A[M,K] @ B[N,K]^T, optional scale+causal -
// 64x64 tile, BK=16, 256 threads, 4x4 per thread
__global__ void gemm_nt_kernel(const float* __restrict__ A, const float* __restrict__ Bm,
                               float* __restrict__ C, int N, int K,
                               long long sA, long long sB, long long sC,
                               float scale, int causal) {
    __shared__ float As[64][17];
    __shared__ float Bs[64][17];
    int bm = blockIdx.x << 6;
    int bn = blockIdx.y << 6;
    if (causal && bn > bm) return;   // fully-masked tile (key-tile entirely > query-tile)
    const float* Ab = A  + sA * (long long)blockIdx.z;
    const float* Bb = Bm + sB * (long long)blockIdx.z;
    float*       Cb = C  + sC * (long long)blockIdx.z;
    int tid = threadIdx.x;
    int tx = tid & 15, ty = tid >> 4;
    int lr = tid >> 2, lc = (tid & 3) << 2;
    float acc[4][4] = {};
    for (int k0 = 0; k0 < K; k0 += 16) {
        float4 av = *(const float4*)(Ab + (size_t)(bm + lr) * K + k0 + lc);
        float4 bv = *(const float4*)(Bb + (size_t)(bn + lr) * K + k0 + lc);
        As[lr][lc+0] = av.x; As[lr][lc+1] = av.y; As[lr][lc+2] = av.z; As[lr][lc+3] = av.w;
        Bs[lr][lc+0] = bv.x; Bs[lr][lc+1] = bv.y; Bs[lr][lc+2] = bv.z; Bs[lr][lc+3] = bv.w;
        __syncthreads();
        #pragma unroll
        for (int k = 0; k < 16; k++) {
            float a0 = As[ty*4+0][k], a1 = As[ty*4+1][k], a2 = As[ty*4+2][k], a3 = As[ty*4+3][k];
            float b0 = Bs[tx*4+0][k], b1 = Bs[tx*4+1][k], b2 = Bs[tx*4+2][k], b3 = Bs[tx*4+3][k];
            acc[0][0] += a0*b0; acc[0][1] += a0*b1; acc[0][2] += a0*b2; acc[0][3] += a0*b3;
            acc[1][0] += a1*b0; acc[1][1] += a1*b1; acc[1][2] += a1*b2; acc[1][3] += a1*b3;
            acc[2][0] += a2*b0; acc[2][1] += a2*b1; acc[2][2] += a2*b2; acc[2][3] += a2*b3;
            acc[3][0] += a3*b0; acc[3][1] += a3*b1; acc[3][2] += a3*b2; acc[3][3] += a3*b3;
        }
        __syncthreads();
    }
    #pragma unroll
    for (int i = 0; i < 4; i++) {
        #pragma unroll
        for (int j = 0; j < 4; j++) {
            int row = bm + ty*4 + i, col = bn + tx*4 + j;
            float v = acc[i][j] * scale;
            if (causal && col > row) v = -1e30f;
            Cb[(size_t)row * N + col] = v;
        }
    }
}

// ---------------- softmax over keys i (axis 0 of ref score) per row ----------
// warp per (b,j) row of g_att; writes full 512 row (0 for i>j)
__global__ void k_softmax() {
    int row  = (blockIdx.x * blockDim.x + threadIdx.x) >> 5;   // 0..BL-1
    int lane = threadIdx.x & 31;
    int j = row & (L_SEQ - 1);
    float* base = g_att + (size_t)row * L_SEQ;
    float vals[16];
    float mx = -1e30f;
    #pragma unroll
    for (int w = 0; w < 16; w++) {
        int i = w * 32 + lane;
        float v = (i <= j) ? base[i] : -1e30f;
        vals[w] = v;
        mx = fmaxf(mx, v);
    }
    mx = warp_max(mx);
    float sum = 0.f;
    #pragma unroll
    for (int w = 0; w < 16; w++) {
        int i = w * 32 + lane;
        float e = (i <= j) ? expf(vals[w] - mx) : 0.f;
        vals[w] = e;
        sum += e;
    }
    sum = warp_sum(sum);
    float inv = 1.f / sum;
    #pragma unroll
    for (int w = 0; w < 16; w++) {
        int i = w * 32 + lane;
        base[i] = vals[w] * inv;
    }
}

// ---------------- GEMM NN: bmat[j,d] = sum_i att[j,i] * v[i,d] per user ------
__global__ void gemm_nn_att_kernel() {
    __shared__ float As[64][17];
    __shared__ float Bs[16][68];
    int bm = blockIdx.x << 6;    // j tile
    int bn = blockIdx.y << 6;    // d tile
    const float* Ab = g_att  + (size_t)blockIdx.z * L_SEQ * L_SEQ;
    const float* Bb = g_v    + (size_t)blockIdx.z * L_SEQ * D;
    float*       Cb = g_bmat + (size_t)blockIdx.z * L_SEQ * D;
    int tid = threadIdx.x;
    int tx = tid & 15, ty = tid >> 4;
    int lrA = tid >> 2,  lcA = (tid & 3)  << 2;
    int lrB = tid >> 4,  lcB = (tid & 15) << 2;
    int kend = bm + 64;          // causal: att[j,i]==0 for i>j, tile rows j<=bm+63
    float acc[4][4] = {};
    for (int k0 = 0; k0 < kend; k0 += 16) {
        float4 av = *(const float4*)(Ab + (size_t)(bm + lrA) * L_SEQ + k0 + lcA);
        float4 bv = *(const float4*)(Bb + (size_t)(k0 + lrB) * D + bn + lcB);
        As[lrA][lcA+0] = av.x; As[lrA][lcA+1] = av.y; As[lrA][lcA+2] = av.z; As[lrA][lcA+3] = av.w;
        Bs[lrB][lcB+0] = bv.x; Bs[lrB][lcB+1] = bv.y; Bs[lrB][lcB+2] = bv.z; Bs[lrB][lcB+3] = bv.w;
        __syncthreads();
        #pragma unroll
        for (int k = 0; k < 16; k++) {
            float a0 = As[ty*4+0][k], a1 = As[ty*4+1][k], a2 = As[ty*4+2][k], a3 = As[ty*4+3][k];
            float b0 = Bs[k][tx*4+0], b1 = Bs[k][tx*4+1], b2 = Bs[k][tx*4+2], b3 = Bs[k][tx*4+3];
            acc[0][0] += a0*b0; acc[0][1] += a0*b1; acc[0][2] += a0*b2; acc[0][3] += a0*b3;
            acc[1][0] += a1*b0; acc[1][1] += a1*b1; acc[1][2] += a1*b2; acc[1][3] += a1*b3;
            acc[2][0] += a2*b0; acc[2][1] += a2*b1; acc[2][2] += a2*b2; acc[2][3] += a2*b3;
            acc[3][0] += a3*b0; acc[3][1] += a3*b1; acc[3][2] += a3*b2; acc[3][3] += a3*b3;
        }
        __syncthreads();
    }
    #pragma unroll
    for (int i = 0; i < 4; i++)
        #pragma unroll
        for (int j = 0; j < 4; j++)
            Cb[(size_t)(bm + ty*4 + i) * D + bn + tx*4 + j] = acc[i][j];
}

// ---------------- sequence BCE loss ------------------------------------------
// warp per (b,t); u = t==0 ? user_init : o[b][t-1]; x = emb[q_seqs[b,t]]
__global__ void k_seqloss(const float4* __restrict__ E4, const float4* __restrict__ uinit4,
                          const int* __restrict__ qseq, const int* __restrict__ cseq) {
    int gw   = (blockIdx.x * blockDim.x + threadIdx.x) >> 5;   // b*L+t
    int lane = threadIdx.x & 31;
    int t = gw & (L_SEQ - 1);
    const float4* u4 = (t == 0) ? uinit4
                                : ((const float4*)g_o) + (size_t)(gw - 1) * (D/4);
    int q = qseq[gw];
    float4 uv = u4[lane];
    float4 xv = E4[(size_t)q * (D/4) + lane];
    float s = uv.x*xv.x + uv.y*xv.y + uv.z*xv.z + uv.w*xv.w;
    s = warp_sum(s);
    float term = 0.f;
    if (lane == 0) {
        float pred = 1.f / (1.f + expf(-s));
        int c = cseq[gw];
        term = c ? logf(pred + EPSF) : logf(1.f - pred + EPSF);
    }
    block_acc(term, 2);
}

// ---------------- combine ----------------------------------------------------
__global__ void k_combine(const float* __restrict__ sd0p, const float* __restrict__ sd1p,
                          const float* __restrict__ sdsp, float* __restrict__ out) {
    if (threadIdx.x == 0 && blockIdx.x == 0) {
        double sd0 = (double)*sd0p, sd1 = (double)*sd1p, sds = (double)*sdsp;
        double l0 = -g_acc[0], l1 = -g_acc[1], ls = -g_acc[2];
        double tf = l0 / (sd0*sd0 + 1e-8) + (double)(2*P0_N)        * log(sd0 + 1e-8)
                  + l1 / (sd1*sd1 + 1e-8) + (double)(P1_N*NEG_MSC*2)* log(sd1 + 1e-8)
                  + ls / (sds*sds + 1e-8) + (double)L_SEQ           * log(sds + 1e-8);
        out[0] = (float)tf;
    }
}

// ---------------- launch -----------------------------------------------------
extern "C" void kernel_launch(void* const* d_in, const int* in_sizes, int n_in,
                              void* d_out, int out_size) {
    const float*  emb   = (const float*)d_in[0];
    const float*  Wrep  = (const float*)d_in[1];
    const float*  Wq    = (const float*)d_in[2];
    const float*  Wk    = (const float*)d_in[3];
    const float*  Wv    = (const float*)d_in[4];
    const float*  Hagg  = (const float*)d_in[5];
    const float*  uinit = (const float*)d_in[6];
    const float*  sd0   = (const float*)d_in[7];
    const float*  sd1   = (const float*)d_in[8];
    const float*  sds   = (const float*)d_in[9];
    const int*    pe0   = (const int*)d_in[10];
    const int*    ne0   = (const int*)d_in[11];
    const int*    pe1   = (const int*)d_in[12];
    const int*    ne1   = (const int*)d_in[13];
    const int*    qseq  = (const int*)d_in[14];
    const int*    cseq  = (const int*)d_in[15];
    (void)in_sizes; (void)n_in; (void)out_size;

    const float4* E4 = (const float4*)emb;
    const float scale = 0.088388347648318447f;   // 1/sqrt(128)

    k_zero<<<1, 32>>>();

    // edge tasks
    k_edge0<<<(2 * P0_N) / 8, 256>>>(E4, (const int2*)pe0, (const int2*)ne0);
    k_edge1<<<(P1_N * NEG_MSC) / 8, 256>>>(E4, (const int2*)pe1, (const int2*)ne1);

    // sequence pipeline
    k_buildI<<<BL / 8, 256>>>(E4, Wrep, qseq, cseq);

    dim3 gp(BL / 64, D / 64, 1);      // (512, 2)
    gemm_nt_kernel<<<gp, 256>>>(g_I, Wq, g_q, D, D, 0, 0, 0, 1.f, 0);
    gemm_nt_kernel<<<gp, 256>>>(g_I, Wk, g_k, D, D, 0, 0, 0, 1.f, 0);
    gemm_nt_kernel<<<gp, 256>>>(g_I, Wv, g_v, D, D, 0, 0, 0, 1.f, 0);

    dim3 gs(L_SEQ / 64, L_SEQ / 64, B_USERS);   // (8, 8, 64), causal tile skip inside
    gemm_nt_kernel<<<gs, 256>>>(g_q, g_k, g_att, L_SEQ, D,
                                (long long)L_SEQ * D, (long long)L_SEQ * D,
                                (long long)L_SEQ * L_SEQ, scale, 1);

    k_softmax<<<BL / 8, 256>>>();

    dim3 gb(L_SEQ / 64, D / 64, B_USERS);       // (8, 2, 64)
    gemm_nn_att_kernel<<<gb, 256>>>();

    gemm_nt_kernel<<<gp, 256>>>(g_bmat, Hagg, g_o, D, D, 0, 0, 0, 1.f, 0);

    k_seqloss<<<BL / 8, 256>>>(E4, (const float4*)uinit, qseq, cseq);

    k_combine<<<1, 32>>>(sd0, sd1, sds, (float*)d_out);
}

// round 3
// speedup vs baseline: 3.5063x; 3.5063x over previous
#include <cuda_runtime.h>
#include <cuda_bf16.h>
#include <math.h>
#include <stdint.h>

typedef unsigned int u32;

// Problem constants
#define N_EMB   50000
#define D       128
#define B_USERS 64
#define L_SEQ   512
#define P0_N    200000
#define P1_N    50000
#define NEG_MSC 4
#define EPSF    1e-8f
#define BL      (B_USERS * L_SEQ)   // 32768
#define LDS     136                  // padded bf16 row stride for 128-wide tiles

// ---------------- scratch ----------------------------------------------------
__device__ double        g_acc[3];
__device__ __nv_bfloat16 g_Ib [BL * D];
__device__ __nv_bfloat16 g_qb [BL * D];
__device__ __nv_bfloat16 g_kb [BL * D];
__device__ __nv_bfloat16 g_vb [BL * D];
__device__ __nv_bfloat16 g_bmb[BL * D];
__device__ float         g_o  [BL * D];
__device__ __nv_bfloat16 g_Wqb[D * D];
__device__ __nv_bfloat16 g_Wkb[D * D];
__device__ __nv_bfloat16 g_Wvb[D * D];
__device__ __nv_bfloat16 g_Hab[D * D];

// ---------------- helpers ----------------------------------------------------
__device__ __forceinline__ float warp_sum(float v) {
    #pragma unroll
    for (int o = 16; o > 0; o >>= 1) v += __shfl_xor_sync(0xffffffffu, v, o);
    return v;
}
__device__ __forceinline__ float logsigf(float x) {
    return logf(1.0f / (1.0f + expf(-x)) + EPSF);
}
__device__ __forceinline__ void block_acc(float term, int accIdx) {
    __shared__ float s_red[8];
    int lane = threadIdx.x & 31, w = threadIdx.x >> 5;
    if (lane == 0) s_red[w] = term;
    __syncthreads();
    if (threadIdx.x == 0) {
        float t = 0.f;
        int nw = blockDim.x >> 5;
        #pragma unroll
        for (int i = 0; i < 8; i++) if (i < nw) t += s_red[i];
        atomicAdd(&g_acc[accIdx], (double)t);
    }
}
__device__ __forceinline__ u32 smem_u32(const void* p) {
    return (u32)__cvta_generic_to_shared(p);
}
__device__ __forceinline__ void mma_bf16(float* c, const u32* a, const u32* b) {
    asm volatile(
        "mma.sync.aligned.m16n8k16.row.col.f32.bf16.bf16.f32 "
        "{%0,%1,%2,%3}, {%4,%5,%6,%7}, {%8,%9}, {%0,%1,%2,%3};\n"
        : "+f"(c[0]), "+f"(c[1]), "+f"(c[2]), "+f"(c[3])
        : "r"(a[0]), "r"(a[1]), "r"(a[2]), "r"(a[3]), "r"(b[0]), "r"(b[1]));
}
__device__ __forceinline__ void ldsm_x4(u32* r, u32 addr) {
    asm volatile("ldmatrix.sync.aligned.m8n8.x4.shared.b16 {%0,%1,%2,%3}, [%4];\n"
        : "=r"(r[0]), "=r"(r[1]), "=r"(r[2]), "=r"(r[3]) : "r"(addr));
}
__device__ __forceinline__ void ldsm_x2(u32* r, u32 addr) {
    asm volatile("ldmatrix.sync.aligned.m8n8.x2.shared.b16 {%0,%1}, [%2];\n"
        : "=r"(r[0]), "=r"(r[1]) : "r"(addr));
}
__device__ __forceinline__ void ldsm_x2t(u32* r, u32 addr) {
    asm volatile("ldmatrix.sync.aligned.m8n8.x2.trans.shared.b16 {%0,%1}, [%2];\n"
        : "=r"(r[0]), "=r"(r[1]) : "r"(addr));
}
__device__ __forceinline__ u32 packbf(float x, float y) {
    __nv_bfloat162 t = __floats2bfloat162_rn(x, y);
    return *(u32*)&t;
}

// ---------------- init -------------------------------------------------------
__global__ void k_zero() {
    if (threadIdx.x < 3) g_acc[threadIdx.x] = 0.0;
}

// ---------------- weight convert fp32 -> bf16 --------------------------------
__global__ void k_cvtW(const float* __restrict__ Wq, const float* __restrict__ Wk,
                       const float* __restrict__ Wv, const float* __restrict__ Ha) {
    int i = blockIdx.x * 256 + threadIdx.x;   // 0..16383
    g_Wqb[i] = __float2bfloat16(Wq[i]);
    g_Wkb[i] = __float2bfloat16(Wk[i]);
    g_Wvb[i] = __float2bfloat16(Wv[i]);
    g_Hab[i] = __float2bfloat16(Ha[i]);
}

// ---------------- edge task 0 ------------------------------------------------
__global__ void k_edge0(const float4* __restrict__ E4,
                        const int2* __restrict__ pe, const int2* __restrict__ ne) {
    int gw   = (blockIdx.x * blockDim.x + threadIdx.x) >> 5;
    int lane = threadIdx.x & 31;
    float term = 0.f;
    if (gw < 2 * P0_N) {
        int2 pr; float sign;
        if (gw < P0_N) { pr = pe[gw];        sign =  1.f; }
        else           { pr = ne[gw - P0_N]; sign = -1.f; }
        float4 av = E4[(size_t)pr.x * (D/4) + lane];
        float4 bv = E4[(size_t)pr.y * (D/4) + lane];
        float p = av.x*bv.x + av.y*bv.y + av.z*bv.z + av.w*bv.w;
        p = warp_sum(p);
        if (lane == 0) term = logsigf(sign * p);
    }
    block_acc(term, 0);
}

// ---------------- edge task 1 ------------------------------------------------
__global__ void k_edge1(const float4* __restrict__ E4,
                        const int2* __restrict__ pe1, const int2* __restrict__ ne1) {
    int gw   = (blockIdx.x * blockDim.x + threadIdx.x) >> 5;
    int lane = threadIdx.x & 31;
    float term = 0.f;
    if (gw < P1_N * NEG_MSC) {
        int j = gw % P1_N;
        int2 pp = pe1[j];
        int2 np = ne1[gw];
        float4 ph = E4[(size_t)pp.x * (D/4) + lane];
        float4 pt = E4[(size_t)pp.y * (D/4) + lane];
        float4 nh = E4[(size_t)np.x * (D/4) + lane];
        float4 nt = E4[(size_t)np.y * (D/4) + lane];
        float sp = ph.x*pt.x + ph.y*pt.y + ph.z*pt.z + ph.w*pt.w;
        float sh = nh.x*pt.x + nh.y*pt.y + nh.z*pt.z + nh.w*pt.w;
        float st = ph.x*nt.x + ph.y*nt.y + ph.z*nt.z + ph.w*nt.w;
        sp = warp_sum(sp); sh = warp_sum(sh); st = warp_sum(st);
        if (lane == 0) term = logsigf(sp - sh) + logsigf(sp - st);
    }
    block_acc(term, 1);
}

// ---------------- build I rows (bf16 out) ------------------------------------
__global__ void k_buildI(const float4* __restrict__ E4, const float* __restrict__ Wrep,
                         const int* __restrict__ qseq, const int* __restrict__ cseq) {
    int row  = (blockIdx.x * blockDim.x + threadIdx.x) >> 5;
    int lane = threadIdx.x & 31;
    int q = qseq[row];
    int c = cseq[row];
    float4 e = E4[(size_t)q * (D/4) + lane];
    int d0 = lane * 4;
    e.x += Wrep[(d0 + 0) * 2 + c];
    e.y += Wrep[(d0 + 1) * 2 + c];
    e.z += Wrep[(d0 + 2) * 2 + c];
    e.w += Wrep[(d0 + 3) * 2 + c];
    uint2 pk;
    pk.x = packbf(e.x, e.y);
    pk.y = packbf(e.z, e.w);
    *(uint2*)(g_Ib + (size_t)row * D + lane * 4) = pk;
}

// ---------------- bf16 NT GEMM: C[M,128] = A[M,128] @ B[128,128]^T ------------
// block: 64 rows of A, 128 threads (4 warps x 16 rows)
__global__ void __launch_bounds__(128) k_gemm_nt(const __nv_bfloat16* __restrict__ A,
                                                 const __nv_bfloat16* __restrict__ Bw,
                                                 void* __restrict__ Cout, int out_bf16) {
    __shared__ __align__(16) __nv_bfloat16 sB[128 * LDS];   // 34816 B
    int tid = threadIdx.x, warp = tid >> 5, lane = tid & 31;
    const __nv_bfloat16* Ab = A + (size_t)blockIdx.x * 64 * D;

    // stage A tile, capture fragments in regs
    for (int i = tid; i < 1024; i += 128) {
        int r = i >> 4, c = (i & 15) << 3;
        *(uint4*)(sB + r * LDS + c) = *(const uint4*)(Ab + r * D + c);
    }
    __syncthreads();
    u32 af[8][4];
    #pragma unroll
    for (int ks = 0; ks < 8; ks++) {
        const __nv_bfloat16* p = sB + (warp * 16 + (lane & 15)) * LDS + ks * 16 + ((lane >> 4) << 3);
        ldsm_x4(af[ks], smem_u32(p));
    }
    __syncthreads();
    // load B (128x128)
    for (int i = tid; i < 2048; i += 128) {
        int r = i >> 4, c = (i & 15) << 3;
        *(uint4*)(sB + r * LDS + c) = *(const uint4*)(Bw + r * D + c);
    }
    __syncthreads();

    float Ca[16][4] = {};
    #pragma unroll
    for (int ks = 0; ks < 8; ks++) {
        #pragma unroll
        for (int nc = 0; nc < 16; nc++) {
            u32 b[2];
            const __nv_bfloat16* p = sB + (nc * 8 + (lane & 7)) * LDS + ks * 16 + ((lane >> 3) & 1) * 8;
            ldsm_x2(b, smem_u32(p));
            mma_bf16(Ca[nc], af[ks], b);
        }
    }

    int r0 = blockIdx.x * 64 + warp * 16 + (lane >> 2);
    int c0 = (lane & 3) << 1;
    if (out_bf16) {
        __nv_bfloat16* C = (__nv_bfloat16*)Cout;
        #pragma unroll
        for (int h = 0; h < 2; h++)
            #pragma unroll
            for (int nc = 0; nc < 16; nc++) {
                u32 pk = packbf(Ca[nc][2*h], Ca[nc][2*h+1]);
                *(u32*)(C + (size_t)(r0 + 8*h) * D + nc * 8 + c0) = pk;
            }
    } else {
        float* C = (float*)Cout;
        #pragma unroll
        for (int h = 0; h < 2; h++)
            #pragma unroll
            for (int nc = 0; nc < 16; nc++) {
                float2 f2 = make_float2(Ca[nc][2*h], Ca[nc][2*h+1]);
                *(float2*)(C + (size_t)(r0 + 8*h) * D + nc * 8 + c0) = f2;
            }
    }
}

// ---------------- fused causal flash attention --------------------------------
// block = (user, query-tile of 64); 128 threads; bf16 mma, fp32 online softmax
__global__ void __launch_bounds__(128) k_flash() {
    __shared__ __align__(16) __nv_bfloat16 sK[64 * LDS];
    __shared__ __align__(16) __nv_bfloat16 sV[64 * LDS];
    int user = blockIdx.x >> 3;
    int jt   = blockIdx.x & 7;
    const __nv_bfloat16* Qb = g_qb + ((size_t)user * L_SEQ + jt * 64) * D;
    const __nv_bfloat16* Kb = g_kb + (size_t)user * L_SEQ * D;
    const __nv_bfloat16* Vb = g_vb + (size_t)user * L_SEQ * D;
    int tid = threadIdx.x, warp = tid >> 5, lane = tid & 31;
    const float scale = 0.08838834764831845f;   // 1/sqrt(128)

    // stage Q into sK, capture fragments in regs
    for (int i = tid; i < 1024; i += 128) {
        int r = i >> 4, c = (i & 15) << 3;
        *(uint4*)(sK + r * LDS + c) = *(const uint4*)(Qb + r * D + c);
    }
    __syncthreads();
    u32 qf[8][4];
    #pragma unroll
    for (int ks = 0; ks < 8; ks++) {
        const __nv_bfloat16* p = sK + (warp * 16 + (lane & 15)) * LDS + ks * 16 + ((lane >> 4) << 3);
        ldsm_x4(qf[ks], smem_u32(p));
    }
    __syncthreads();

    float Oa[16][4] = {};
    float mrow[2] = {-1e30f, -1e30f};
    float lrow[2] = {0.f, 0.f};

    for (int kt = 0; kt <= jt; kt++) {
        for (int i = tid; i < 1024; i += 128) {
            int r = i >> 4, c = (i & 15) << 3;
            *(uint4*)(sK + r * LDS + c) = *(const uint4*)(Kb + (size_t)(kt * 64 + r) * D + c);
            *(uint4*)(sV + r * LDS + c) = *(const uint4*)(Vb + (size_t)(kt * 64 + r) * D + c);
        }
        __syncthreads();

        // S = Q @ K^T (per warp: 16 x 64)
        float S[8][4] = {};
        #pragma unroll
        for (int ks = 0; ks < 8; ks++) {
            #pragma unroll
            for (int nc = 0; nc < 8; nc++) {
                u32 b[2];
                const __nv_bfloat16* p = sK + (nc * 8 + (lane & 7)) * LDS + ks * 16 + ((lane >> 3) & 1) * 8;
                ldsm_x2(b, smem_u32(p));
                mma_bf16(S[nc], qf[ks], b);
            }
        }
        #pragma unroll
        for (int nc = 0; nc < 8; nc++) {
            S[nc][0] *= scale; S[nc][1] *= scale; S[nc][2] *= scale; S[nc][3] *= scale;
        }
        if (kt == jt) {   // causal mask: col > row
            int r0 = warp * 16 + (lane >> 2);
            #pragma unroll
            for (int nc = 0; nc < 8; nc++) {
                int c0 = nc * 8 + ((lane & 3) << 1);
                if (c0     > r0    ) S[nc][0] = -1e30f;
                if (c0 + 1 > r0    ) S[nc][1] = -1e30f;
                if (c0     > r0 + 8) S[nc][2] = -1e30f;
                if (c0 + 1 > r0 + 8) S[nc][3] = -1e30f;
            }
        }

        // online softmax over the two fragment rows
        #pragma unroll
        for (int h = 0; h < 2; h++) {
            float vmax = -1e30f;
            #pragma unroll
            for (int nc = 0; nc < 8; nc++)
                vmax = fmaxf(vmax, fmaxf(S[nc][2*h], S[nc][2*h+1]));
            vmax = fmaxf(vmax, __shfl_xor_sync(0xffffffffu, vmax, 1));
            vmax = fmaxf(vmax, __shfl_xor_sync(0xffffffffu, vmax, 2));
            float mnew = fmaxf(mrow[h], vmax);
            float corr = __expf(mrow[h] - mnew);
            mrow[h] = mnew;
            float rsum = 0.f;
            #pragma unroll
            for (int nc = 0; nc < 8; nc++) {
                float p0 = __expf(S[nc][2*h]   - mnew);
                float p1 = __expf(S[nc][2*h+1] - mnew);
                S[nc][2*h] = p0; S[nc][2*h+1] = p1;
                rsum += p0 + p1;
            }
            rsum += __shfl_xor_sync(0xffffffffu, rsum, 1);
            rsum += __shfl_xor_sync(0xffffffffu, rsum, 2);
            lrow[h] = lrow[h] * corr + rsum;
            #pragma unroll
            for (int nc = 0; nc < 16; nc++) {
                Oa[nc][2*h]   *= corr;
                Oa[nc][2*h+1] *= corr;
            }
        }

        // O += P @ V  (P 16x64 in regs -> A frags; V via trans ldmatrix)
        #pragma unroll
        for (int s = 0; s < 4; s++) {
            u32 a[4];
            a[0] = packbf(S[2*s][0],   S[2*s][1]);
            a[1] = packbf(S[2*s][2],   S[2*s][3]);
            a[2] = packbf(S[2*s+1][0], S[2*s+1][1]);
            a[3] = packbf(S[2*s+1][2], S[2*s+1][3]);
            #pragma unroll
            for (int nc = 0; nc < 16; nc++) {
                u32 b[2];
                const __nv_bfloat16* p = sV + (s * 16 + (lane & 7) + ((lane >> 3) & 1) * 8) * LDS + nc * 8;
                ldsm_x2t(b, smem_u32(p));
                mma_bf16(Oa[nc], a, b);
            }
        }
        __syncthreads();
    }

    // epilogue: normalize, write bmat bf16
    int r_local = warp * 16 + (lane >> 2);
    int c0 = (lane & 3) << 1;
    size_t obase = ((size_t)user * L_SEQ + jt * 64) * D;
    #pragma unroll
    for (int h = 0; h < 2; h++) {
        float inv = 1.f / lrow[h];
        size_t rb = obase + (size_t)(r_local + 8 * h) * D;
        #pragma unroll
        for (int nc = 0; nc < 16; nc++) {
            u32 pk = packbf(Oa[nc][2*h] * inv, Oa[nc][2*h+1] * inv);
            *(u32*)(g_bmb + rb + nc * 8 + c0) = pk;
        }
    }
}

// ---------------- sequence BCE loss ------------------------------------------
__global__ void k_seqloss(const float4* __restrict__ E4, const float4* __restrict__ uinit4,
                          const int* __restrict__ qseq, const int* __restrict__ cseq) {
    int gw   = (blockIdx.x * blockDim.x + threadIdx.x) >> 5;
    int lane = threadIdx.x & 31;
    int t = gw & (L_SEQ - 1);
    const float4* u4 = (t == 0) ? uinit4
                                : ((const float4*)g_o) + (size_t)(gw - 1) * (D/4);
    int q = qseq[gw];
    float4 uv = u4[lane];
    float4 xv = E4[(size_t)q * (D/4) + lane];
    float s = uv.x*xv.x + uv.y*xv.y + uv.z*xv.z + uv.w*xv.w;
    s = warp_sum(s);
    float term = 0.f;
    if (lane == 0) {
        float pred = 1.f / (1.f + expf(-s));
        int c = cseq[gw];
        term = c ? logf(pred + EPSF) : logf(1.f - pred + EPSF);
    }
    block_acc(term, 2);
}

// ---------------- combine ----------------------------------------------------
__global__ void k_combine(const float* __restrict__ sd0p, const float* __restrict__ sd1p,
                          const float* __restrict__ sdsp, float* __restrict__ out) {
    if (threadIdx.x == 0 && blockIdx.x == 0) {
        double sd0 = (double)*sd0p, sd1 = (double)*sd1p, sds = (double)*sdsp;
        double l0 = -g_acc[0], l1 = -g_acc[1], ls = -g_acc[2];
        double tf = l0 / (sd0*sd0 + 1e-8) + (double)(2*P0_N)         * log(sd0 + 1e-8)
                  + l1 / (sd1*sd1 + 1e-8) + (double)(P1_N*NEG_MSC*2) * log(sd1 + 1e-8)
                  + ls / (sds*sds + 1e-8) + (double)L_SEQ            * log(sds + 1e-8);
        out[0] = (float)tf;
    }
}

// ---------------- launch -----------------------------------------------------
extern "C" void kernel_launch(void* const* d_in, const int* in_sizes, int n_in,
                              void* d_out, int out_size) {
    const float*  emb   = (const float*)d_in[0];
    const float*  Wrep  = (const float*)d_in[1];
    const float*  Wq    = (const float*)d_in[2];
    const float*  Wk    = (const float*)d_in[3];
    const float*  Wv    = (const float*)d_in[4];
    const float*  Hagg  = (const float*)d_in[5];
    const float*  uinit = (const float*)d_in[6];
    const float*  sd0   = (const float*)d_in[7];
    const float*  sd1   = (const float*)d_in[8];
    const float*  sds   = (const float*)d_in[9];
    const int*    pe0   = (const int*)d_in[10];
    const int*    ne0   = (const int*)d_in[11];
    const int*    pe1   = (const int*)d_in[12];
    const int*    ne1   = (const int*)d_in[13];
    const int*    qseq  = (const int*)d_in[14];
    const int*    cseq  = (const int*)d_in[15];
    (void)in_sizes; (void)n_in; (void)out_size;

    const float4* E4 = (const float4*)emb;

    k_zero<<<1, 32>>>();
    k_cvtW<<<64, 256>>>(Wq, Wk, Wv, Hagg);

    // edge tasks (independent)
    k_edge0<<<(2 * P0_N) / 8, 256>>>(E4, (const int2*)pe0, (const int2*)ne0);
    k_edge1<<<(P1_N * NEG_MSC) / 8, 256>>>(E4, (const int2*)pe1, (const int2*)ne1);

    // sequence pipeline
    k_buildI<<<BL / 8, 256>>>(E4, Wrep, qseq, cseq);

    k_gemm_nt<<<BL / 64, 128>>>(g_Ib, g_Wqb, g_qb, 1);
    k_gemm_nt<<<BL / 64, 128>>>(g_Ib, g_Wkb, g_kb, 1);
    k_gemm_nt<<<BL / 64, 128>>>(g_Ib, g_Wvb, g_vb, 1);

    k_flash<<<B_USERS * 8, 128>>>();

    k_gemm_nt<<<BL / 64, 128>>>(g_bmb, g_Hab, g_o, 0);

    k_seqloss<<<BL / 8, 256>>>(E4, (const float4*)uinit, qseq, cseq);

    k_combine<<<1, 32>>>(sd0, sd1, sds, (float*)d_out);
}